// round 16
// baseline (speedup 1.0000x reference)
#include <cuda_runtime.h>
#include <cuda_fp16.h>
#include <cstdint>

#define NVOX (128*128*128)
#define EPSV 1e-5f
#define SLOPE 0.01f

// ---------------- device globals ----------------
static __device__ float g_buf0[16*NVOX];
static __device__ float g_buf1[16*NVOX];
static __device__ __align__(16) unsigned char g_mask[NVOX];
// per-layer weights [tap][o][k] fp16 hi/lo : 27*16*16 = 6912 halfs
static __device__ __align__(16) __half g_wfh[4][6912];
static __device__ __align__(16) __half g_wfl[4][6912];
static __device__ float g_sum[5][16];
static __device__ float g_sq[5][16];
static __device__ int   g_cnt;

// ---------------- helpers ----------------
__device__ __forceinline__ uint32_t smem_u32(const void* p){
  uint32_t a;
  asm("{ .reg .u64 t; cvta.to.shared.u64 t, %1; cvt.u32.u64 %0, t; }" : "=r"(a) : "l"(p));
  return a;
}
__device__ __forceinline__ float warp_sum(float v){
#pragma unroll
  for (int o = 16; o; o >>= 1) v += __shfl_xor_sync(0xffffffffu, v, o);
  return v;
}
__device__ __forceinline__ void ldm4(uint32_t* r, uint32_t a){
  asm volatile("ldmatrix.sync.aligned.m8n8.x4.shared.b16 {%0,%1,%2,%3}, [%4];"
    : "=r"(r[0]), "=r"(r[1]), "=r"(r[2]), "=r"(r[3]) : "r"(a));
}
__device__ __forceinline__ void mma16816(float* c, const uint32_t* a, const uint32_t* b){
  asm volatile("mma.sync.aligned.m16n8k16.row.col.f32.f16.f16.f32 "
    "{%0,%1,%2,%3}, {%4,%5,%6,%7}, {%8,%9}, {%0,%1,%2,%3};"
    : "+f"(c[0]), "+f"(c[1]), "+f"(c[2]), "+f"(c[3])
    : "r"(a[0]), "r"(a[1]), "r"(a[2]), "r"(a[3]), "r"(b[0]), "r"(b[1]));
}

// ---------------- trivial kernels ----------------
__global__ void k_zero(){
  int t = threadIdx.x;
  if (t < 80){ (&g_sum[0][0])[t] = 0.f; (&g_sq[0][0])[t] = 0.f; }
  if (t == 0) g_cnt = 0;
}

// Repack 3x3x3 weights [o][c][tap] -> [tap][o][k=c] fp16 hi/lo
__global__ void k_pack(const float* __restrict__ w1, const float* __restrict__ w2,
                       const float* __restrict__ w3, const float* __restrict__ w4){
  int l = blockIdx.x;
  const float* w = l == 0 ? w1 : l == 1 ? w2 : l == 2 ? w3 : w4;
  for (int i = threadIdx.x; i < 6912; i += 256){
    int tap = i >> 8, o = (i >> 4) & 15, c = i & 15;
    float v = w[(o*16 + c)*27 + tap];
    __half hi = __float2half(v);
    __half lo = __float2half(v - __half2float(hi));
    g_wfh[l][i] = hi; g_wfl[l][i] = lo;
  }
}

// Layer 0: mask gen + active count + 1x1 conv (4->16) + masked stats
__global__ void __launch_bounds__(256) k_init(
    const float* __restrict__ feat, const int* __restrict__ maski,
    const float* __restrict__ w0, const float* __restrict__ b0)
{
  __shared__ float s_w[64];
  __shared__ float s_b[16];
  __shared__ float s_red[32];
  __shared__ int s_cnt;
  int tid = threadIdx.x;
  if (tid < 64) s_w[tid] = w0[(tid & 15) * 4 + (tid >> 4)];
  if (tid < 16) s_b[tid] = b0[tid];
  if (tid < 32) s_red[tid] = 0.f;
  if (tid == 0) s_cnt = 0;
  __syncthreads();

  int p = (blockIdx.x * 256 + tid) * 4;
  float xf[4][4];
#pragma unroll
  for (int c = 0; c < 4; c++){
    float4 t4 = *(const float4*)(feat + c * NVOX + p);
    xf[c][0] = t4.x; xf[c][1] = t4.y; xf[c][2] = t4.z; xf[c][3] = t4.w;
  }
  int4 mi = *(const int4*)(maski + p);
  float m[4] = { mi.x > 0 ? 1.f : 0.f, mi.y > 0 ? 1.f : 0.f,
                 mi.z > 0 ? 1.f : 0.f, mi.w > 0 ? 1.f : 0.f };
  *(uchar4*)(g_mask + p) = make_uchar4((unsigned char)m[0], (unsigned char)m[1],
                                       (unsigned char)m[2], (unsigned char)m[3]);
  int cnt = (int)(m[0] + m[1] + m[2] + m[3]);

  float ps[16], pq[16];
#pragma unroll
  for (int o = 0; o < 16; o++){
    float y[4];
#pragma unroll
    for (int v = 0; v < 4; v++){
      float a = s_b[o];
#pragma unroll
      for (int c = 0; c < 4; c++) a = fmaf(s_w[c*16 + o], xf[c][v], a);
      y[v] = a * m[v];
    }
    *(float4*)(g_buf0 + o*NVOX + p) = make_float4(y[0], y[1], y[2], y[3]);
    ps[o] = (y[0] + y[1]) + (y[2] + y[3]);
    pq[o] = (y[0]*y[0] + y[1]*y[1]) + (y[2]*y[2] + y[3]*y[3]);
  }
#pragma unroll
  for (int o = 0; o < 16; o++){
    float s = warp_sum(ps[o]);
    float q = warp_sum(pq[o]);
    if ((tid & 31) == 0){ atomicAdd(&s_red[o], s); atomicAdd(&s_red[16 + o], q); }
  }
  {
    int c2 = cnt;
#pragma unroll
    for (int o = 16; o; o >>= 1) c2 += __shfl_xor_sync(0xffffffffu, c2, o);
    if ((tid & 31) == 0) atomicAdd(&s_cnt, c2);
  }
  __syncthreads();
  if (tid < 16)      atomicAdd(&g_sum[0][tid], s_red[tid]);
  else if (tid < 32) atomicAdd(&g_sq[0][tid - 16], s_red[tid]);
  if (tid == 0) atomicAdd(&g_cnt, s_cnt);
}

// ---------------- mma.sync conv layer ----------------
// One CTA = 16x8x1 output tile (M=128 voxels), 128 threads (4 warps).
// Halo 18x10x3 x 16c fp16 hi/lo, record stride 48B (16B-aligned ldmatrix rows,
// conflict-free banks). Warp w owns m-frags {2w, 2w+1} (y rows), all 16 outs.
// Per tap: A via ldmatrix.x4 (hi,lo per frag), B via broadcast LDS, 12 HMMA.
#define SM_WH    0          // 13824 : weights hi [tap][o][k]
#define SM_WL    13824      // 13824 : weights lo
#define SM_HHI   27648      // 25920 : halo hi, 540 pos x 48B
#define SM_HLO   53568      // 25920 : halo lo
#define SM_SA    79488
#define SM_SC    79552
#define SM_SB    79616
#define SM_SRED  79680      // 32 floats
#define SM_TOTAL 79808
__global__ void __launch_bounds__(128, 2) k_conv_m(
    int dir, int stage,
    const float* __restrict__ b,
    const float* __restrict__ gamma_p, const float* __restrict__ beta_p)
{
  extern __shared__ char sm[];
  uint32_t smb = smem_u32(sm);
  int tid = threadIdx.x;
  int warp = tid >> 5, lane = tid & 31;

  const float* in  = dir ? g_buf1 : g_buf0;
  float*       out = dir ? g_buf0 : g_buf1;
  const float* sum_p = g_sum[stage - 1];
  const float* sq_p  = g_sq[stage - 1];
  float* sum_c = g_sum[stage];
  float* sq_c  = g_sq[stage];

  float* s_a   = (float*)(sm + SM_SA);
  float* s_c   = (float*)(sm + SM_SC);
  float* s_b   = (float*)(sm + SM_SB);
  float* s_red = (float*)(sm + SM_SRED);

  if (tid < 16){
    float n = (float)g_cnt;
    float mean = sum_p[tid] / n;
    float var = sq_p[tid] / n - mean * mean;
    float a = gamma_p[tid] * rsqrtf(var + EPSV);
    s_a[tid] = a;
    s_c[tid] = beta_p[tid] - mean * a;
    s_b[tid] = b[tid];
  }
  if (tid < 32) s_red[tid] = 0.f;
  // weights -> smem
  {
    const float4* srcH = (const float4*)g_wfh[stage - 1];
    const float4* srcL = (const float4*)g_wfl[stage - 1];
    float4* dstH = (float4*)(sm + SM_WH);
    float4* dstL = (float4*)(sm + SM_WL);
    for (int i = tid; i < 864; i += 128){ dstH[i] = srcH[i]; dstL[i] = srcL[i]; }
  }
  __syncthreads();   // s_a/s_c ready for fill

  int bid = blockIdx.x;
  int ox0 = (bid & 7) * 16;
  int oy0 = ((bid >> 3) & 15) * 8;
  int oz  = bid >> 7;

  // fill halo: thread owns channel c = tid>>3, strides pos by 8 (x-coalesced)
  {
    int c = tid >> 3;
    float ac = s_a[c], cc = s_c[c];
    __half* hh = (__half*)(sm + SM_HHI);
    __half* hl = (__half*)(sm + SM_HLO);
    for (int pos = tid & 7; pos < 540; pos += 8){
      int z = pos / 180, r2 = pos % 180;
      int y = r2 / 18, x = r2 % 18;
      int gx = ox0 + x - 1, gy = oy0 + y - 1, gz = oz + z - 1;
      float val = 0.f;
      if ((unsigned)gx < 128u && (unsigned)gy < 128u && (unsigned)gz < 128u){
        int gp = (gz*128 + gy)*128 + gx;
        if (g_mask[gp]){
          float v = fmaf(ac, in[c*NVOX + gp], cc);
          val = v >= 0.f ? v : SLOPE * v;
        }
      }
      __half hi = __float2half(val);
      __half lo = __float2half(val - __half2float(hi));
      hh[pos*24 + c] = hi;   // 48B record stride
      hl[pos*24 + c] = lo;
    }
  }
  __syncthreads();

  // C fragments [mfrag][nfrag][4]
  float C[2][2][4];
#pragma unroll
  for (int i = 0; i < 2; i++)
#pragma unroll
    for (int j = 0; j < 2; j++)
#pragma unroll
      for (int r = 0; r < 4; r++) C[i][j][r] = 0.f;

  // ldmatrix lane geometry
  int g8 = lane >> 3;
  int mi = (lane & 7) + ((g8 & 1) << 3);   // row voxel x
  int koff = (g8 >> 1) << 4;               // +16B for k8..15
  // B lane geometry
  int bn = lane >> 2, bk0 = (lane & 3) << 1;

#pragma unroll 1
  for (int i = 0; i < 27; i++){
    int dz = i / 9, r3 = i % 9, dy = r3 / 3, dx = r3 % 3;
    uint32_t Ah[2][4], Al[2][4];
#pragma unroll
    for (int mf = 0; mf < 2; mf++){
      int f = 2*warp + mf;
      int pos = dz*180 + (f + dy)*18 + (mi + dx);
      uint32_t ad = smb + (uint32_t)(SM_HHI) + (uint32_t)pos*48u + (uint32_t)koff;
      ldm4(Ah[mf], ad);
      ldm4(Al[mf], ad + (SM_HLO - SM_HHI));
    }
    uint32_t Bh[2][2], Bl[2][2];
#pragma unroll
    for (int nf = 0; nf < 2; nf++){
      int o = bn + nf*8;
      int off = (i*256 + o*16 + bk0) * 2;
      Bh[nf][0] = *(const uint32_t*)(sm + SM_WH + off);
      Bh[nf][1] = *(const uint32_t*)(sm + SM_WH + off + 16);
      Bl[nf][0] = *(const uint32_t*)(sm + SM_WL + off);
      Bl[nf][1] = *(const uint32_t*)(sm + SM_WL + off + 16);
    }
#pragma unroll
    for (int mf = 0; mf < 2; mf++)
#pragma unroll
      for (int nf = 0; nf < 2; nf++){
        mma16816(C[mf][nf], Ah[mf], Bh[nf]);   // hi*hi
        mma16816(C[mf][nf], Ah[mf], Bl[nf]);   // hi*lo
        mma16816(C[mf][nf], Al[mf], Bh[nf]);   // lo*hi
      }
  }

  // epilogue: bias + mask + store + stats
  float psl[4] = {0.f, 0.f, 0.f, 0.f}, pql[4] = {0.f, 0.f, 0.f, 0.f};
#pragma unroll
  for (int mf = 0; mf < 2; mf++){
    int f = 2*warp + mf;
#pragma unroll
    for (int h = 0; h < 2; h++){
      int x = (lane >> 2) + h*8;
      int gp = (oz*128 + oy0 + f)*128 + ox0 + x;
      float m = g_mask[gp] ? 1.f : 0.f;
#pragma unroll
      for (int nf = 0; nf < 2; nf++)
#pragma unroll
        for (int d = 0; d < 2; d++){
          int o = ((lane & 3) << 1) + d + nf*8;
          float val = (C[mf][nf][h*2 + d] + s_b[o]) * m;
          out[o*NVOX + gp] = val;
          psl[nf*2 + d] += val;
          pql[nf*2 + d] += val * val;
        }
    }
  }
#pragma unroll
  for (int idx = 0; idx < 4; idx++){
#pragma unroll
    for (int off = 4; off < 32; off <<= 1){
      psl[idx] += __shfl_xor_sync(0xffffffffu, psl[idx], off);
      pql[idx] += __shfl_xor_sync(0xffffffffu, pql[idx], off);
    }
  }
  if (lane < 4){
#pragma unroll
    for (int nf = 0; nf < 2; nf++)
#pragma unroll
      for (int d = 0; d < 2; d++){
        int o = lane*2 + d + nf*8;
        atomicAdd(&s_red[o],      psl[nf*2 + d]);
        atomicAdd(&s_red[16 + o], pql[nf*2 + d]);
      }
  }
  __syncthreads();
  if (tid < 16)      atomicAdd(&sum_c[tid], s_red[tid]);
  else if (tid < 32) atomicAdd(&sq_c[tid - 16], s_red[tid]);
}

// Final: BN4+act+mask on load, 1x1 conv (16->16) + b5, mask, write y + mask plane
__global__ void __launch_bounds__(256) k_final(
    const float* __restrict__ w5, const float* __restrict__ b5,
    const float* __restrict__ gamma_p, const float* __restrict__ beta_p,
    float* __restrict__ outp)
{
  __shared__ float s_w[256];
  __shared__ float s_a[16], s_c[16], s_b[16];
  const float* in = g_buf0;
  const float* sum_p = g_sum[4];
  const float* sq_p  = g_sq[4];
  int tid = threadIdx.x;
  s_w[tid] = w5[(tid & 15)*16 + (tid >> 4)];
  if (tid < 16){
    float n = (float)g_cnt;
    float mean = sum_p[tid] / n;
    float var = sq_p[tid] / n - mean * mean;
    float a = gamma_p[tid] * rsqrtf(var + EPSV);
    s_a[tid] = a; s_c[tid] = beta_p[tid] - mean * a; s_b[tid] = b5[tid];
  }
  __syncthreads();
  int p = (blockIdx.x*256 + tid) * 4;
  uchar4 mu = *(const uchar4*)(g_mask + p);
  float m[4] = { (float)mu.x, (float)mu.y, (float)mu.z, (float)mu.w };
  float acc[64];
#pragma unroll
  for (int o = 0; o < 16; o++){
    float bb = s_b[o];
    acc[o*4+0] = bb; acc[o*4+1] = bb; acc[o*4+2] = bb; acc[o*4+3] = bb;
  }
#pragma unroll 1
  for (int c = 0; c < 16; c++){
    float4 t4 = *(const float4*)(in + c*NVOX + p);
    float z[4] = { t4.x, t4.y, t4.z, t4.w };
    float a = s_a[c], cc = s_c[c];
#pragma unroll
    for (int v = 0; v < 4; v++){
      float u = fmaf(a, z[v], cc);
      u = u >= 0.f ? u : SLOPE * u;
      z[v] = u * m[v];
    }
    const float4* wp = (const float4*)(s_w + c*16);
    float4 wa = wp[0], wb = wp[1], wc4 = wp[2], wd = wp[3];
    float wv[16] = { wa.x, wa.y, wa.z, wa.w,  wb.x, wb.y, wb.z, wb.w,
                     wc4.x, wc4.y, wc4.z, wc4.w,  wd.x, wd.y, wd.z, wd.w };
#pragma unroll
    for (int o = 0; o < 16; o++)
#pragma unroll
      for (int v = 0; v < 4; v++) acc[o*4+v] = fmaf(wv[o], z[v], acc[o*4+v]);
  }
#pragma unroll
  for (int o = 0; o < 16; o++)
    *(float4*)(outp + o*NVOX + p) = make_float4(acc[o*4+0]*m[0], acc[o*4+1]*m[1],
                                                acc[o*4+2]*m[2], acc[o*4+3]*m[3]);
  *(float4*)(outp + 16*NVOX + p) = make_float4(m[0], m[1], m[2], m[3]);
}

extern "C" void kernel_launch(void* const* d_in, const int* in_sizes, int n_in,
                              void* d_out, int out_size){
  (void)in_sizes; (void)n_in; (void)out_size;
  const float* feat  = (const float*)d_in[0];
  const int*   maski = (const int*)d_in[1];
  const float* w0 = (const float*)d_in[2];
  const float* b0 = (const float*)d_in[3];
  const float* g0 = (const float*)d_in[4];
  const float* be0= (const float*)d_in[5];
  const float* W[4]; const float* Bv[4]; const float* G[4]; const float* BE[4];
  for (int i = 0; i < 4; i++){
    W[i]  = (const float*)d_in[6 + 4*i];
    Bv[i] = (const float*)d_in[7 + 4*i];
    G[i]  = (const float*)d_in[8 + 4*i];
    BE[i] = (const float*)d_in[9 + 4*i];
  }
  const float* w5 = (const float*)d_in[22];
  const float* b5 = (const float*)d_in[23];
  float* outp = (float*)d_out;

  cudaFuncSetAttribute(k_conv_m, cudaFuncAttributeMaxDynamicSharedMemorySize, SM_TOTAL);

  k_zero<<<1, 128>>>();
  k_pack<<<4, 256>>>(W[0], W[1], W[2], W[3]);
  k_init<<<2048, 256>>>(feat, maski, w0, b0);
  k_conv_m<<<16384, 128, SM_TOTAL>>>(0, 1, Bv[0], g0,   be0);
  k_conv_m<<<16384, 128, SM_TOTAL>>>(1, 2, Bv[1], G[0], BE[0]);
  k_conv_m<<<16384, 128, SM_TOTAL>>>(0, 3, Bv[2], G[1], BE[1]);
  k_conv_m<<<16384, 128, SM_TOTAL>>>(1, 4, Bv[3], G[2], BE[2]);
  k_final<<<2048, 256>>>(w5, b5, G[3], BE[3], outp);
}